// round 5
// baseline (speedup 1.0000x reference)
#include <cuda_runtime.h>
#include <stdint.h>
#include <math.h>

#define BSZ 8
#define H   512
#define P   128
#define LSEQ 8192

// -------- scratch (__device__ globals; allocation-free rule) ----------------
__device__ float2 g_Bu[(size_t)BSZ * P * LSEQ];        // Bu complex interleaved, 67 MB
__device__ float  g_X[(size_t)2 * BSZ * P * LSEQ];     // xs split planes [side][b][p][l], 67 MB
__device__ float  g_BreT[H * P];                       // B_bar re, [h][p]
__device__ float  g_BimT[H * P];                       // B_bar im, [h][p]
__device__ float2 g_Lbar[P];
__device__ float  g_A2T[2 * P * H];                    // folded C, [k][h]: k<128 -> 2*Cre, else -2*Cim

__device__ __forceinline__ float2 cmul(float2 a, float2 b) {
    return make_float2(a.x * b.x - a.y * b.y, a.x * b.y + a.y * b.x);
}

__device__ __forceinline__ void cp16(void* s, const void* g) {
    unsigned int sa = (unsigned int)__cvta_generic_to_shared(s);
    asm volatile("cp.async.cg.shared.global [%0], [%1], 16;\n" :: "r"(sa), "l"(g));
}
__device__ __forceinline__ void cp_commit() { asm volatile("cp.async.commit_group;\n"); }
__device__ __forceinline__ void cp_wait0()  { asm volatile("cp.async.wait_group 0;\n"); }

// ---------------------------------------------------------------------------
// Setup: Lambda_bar, transposed B_bar planes, folded transposed C (fp64 math).
// ---------------------------------------------------------------------------
__global__ void setup_kernel(const float* __restrict__ Lre, const float* __restrict__ Lim,
                             const float* __restrict__ Bm, const float* __restrict__ Cm,
                             const float* __restrict__ logstep) {
    int tid = blockIdx.x * blockDim.x + threadIdx.x;
    int stride = gridDim.x * blockDim.x;

    if (tid < P) {
        double st = exp((double)logstep[tid]);
        double zre = (double)Lre[tid] * st, zim = (double)Lim[tid] * st;
        double er = exp(zre);
        g_Lbar[tid] = make_float2((float)(er * cos(zim)), (float)(er * sin(zim)));
    }

    for (int i = tid; i < P * H; i += stride) {
        int p = i >> 9, h = i & (H - 1);
        double st  = exp((double)logstep[p]);
        double lre = (double)Lre[p], lim = (double)Lim[p];
        double zre = lre * st, zim = lim * st;
        double er  = exp(zre);
        double numr = er * cos(zim) - 1.0;
        double numi = er * sin(zim);
        double den  = lre * lre + lim * lim;
        double gre = (numr * lre + numi * lim) / den;
        double gim = (numi * lre - numr * lim) / den;
        float br = Bm[2 * i], bi = Bm[2 * i + 1];
        g_BreT[h * P + p] = (float)(gre * (double)br - gim * (double)bi);
        g_BimT[h * P + p] = (float)(gre * (double)bi + gim * (double)br);
    }

    for (int i = tid; i < 2 * P * H; i += stride) {
        int k = i >> 9, h = i & (H - 1);          // row k, col h
        float v;
        if (k < P) v =  2.0f * Cm[(h * P + k) * 2];
        else       v = -2.0f * Cm[(h * P + (k - P)) * 2 + 1];
        g_A2T[(size_t)k * H + h] = v;
    }
}

// ---------------------------------------------------------------------------
// K1: Bu[b,p,l] = sum_h Bbar[p,h]*u[b,h,l].  BM=128(p) BN=64(l) BK=16(h),
// 256 thr, 8x4 complex microtile (64 fp32 accums), double-buffered cp.async.
// ---------------------------------------------------------------------------
__global__ void __launch_bounds__(256) bu_gemm_kernel(const float* __restrict__ u) {
    const int b  = blockIdx.z;
    const int n0 = blockIdx.x * 64;
    const int tx = threadIdx.x & 15;   // n: 4 l
    const int ty = threadIdx.x >> 4;   // m: ty*4..+3 and +64

    __shared__ __align__(16) float Are[2][16][128];
    __shared__ __align__(16) float Aim[2][16][128];
    __shared__ __align__(16) float Us [2][16][64];

    const float* ub = u + (size_t)b * H * LSEQ;

    auto load_stage = [&](int buf, int k0) {
        for (int s = threadIdx.x; s < 512; s += 256) {
            int k = s >> 5, c = (s & 31) * 4;
            cp16(&Are[buf][k][c], g_BreT + (size_t)(k0 + k) * P + c);
            cp16(&Aim[buf][k][c], g_BimT + (size_t)(k0 + k) * P + c);
        }
        {
            int s = threadIdx.x;
            int k = s >> 4, c = (s & 15) * 4;
            cp16(&Us[buf][k][c], ub + (size_t)(k0 + k) * LSEQ + n0 + c);
        }
        cp_commit();
    };

    float2 acc[8][4];
#pragma unroll
    for (int m = 0; m < 8; m++)
#pragma unroll
        for (int n = 0; n < 4; n++) acc[m][n] = make_float2(0.f, 0.f);

    load_stage(0, 0);
    int buf = 0;
    for (int k0 = 0; k0 < H; k0 += 16) {
        cp_wait0();
        __syncthreads();
        if (k0 + 16 < H) load_stage(buf ^ 1, k0 + 16);

#pragma unroll
        for (int kk = 0; kk < 16; kk++) {
            float4 r0 = *(const float4*)&Are[buf][kk][ty * 4];
            float4 r1 = *(const float4*)&Are[buf][kk][ty * 4 + 64];
            float4 i0 = *(const float4*)&Aim[buf][kk][ty * 4];
            float4 i1 = *(const float4*)&Aim[buf][kk][ty * 4 + 64];
            float4 uu = *(const float4*)&Us[buf][kk][tx * 4];
            float ar[8] = {r0.x, r0.y, r0.z, r0.w, r1.x, r1.y, r1.z, r1.w};
            float ai[8] = {i0.x, i0.y, i0.z, i0.w, i1.x, i1.y, i1.z, i1.w};
            float un[4] = {uu.x, uu.y, uu.z, uu.w};
#pragma unroll
            for (int m = 0; m < 8; m++)
#pragma unroll
                for (int n = 0; n < 4; n++) {
                    acc[m][n].x += ar[m] * un[n];
                    acc[m][n].y += ai[m] * un[n];
                }
        }
        __syncthreads();
        buf ^= 1;
    }

#pragma unroll
    for (int m = 0; m < 8; m++) {
        int p = (m < 4) ? (ty * 4 + m) : (ty * 4 + 64 + m - 4);
        float2* dst = g_Bu + (size_t)(b * P + p) * LSEQ + n0 + tx * 4;
        float4* d4 = (float4*)dst;
        d4[0] = make_float4(acc[m][0].x, acc[m][0].y, acc[m][1].x, acc[m][1].y);
        d4[1] = make_float4(acc[m][2].x, acc[m][2].y, acc[m][3].x, acc[m][3].y);
    }
}

// ---------------------------------------------------------------------------
// K2: scan along L; warp-shuffle Kogge-Stone (2 barriers). Split-plane output.
// ---------------------------------------------------------------------------
__global__ void __launch_bounds__(512) scan_kernel() {
    const int seq = blockIdx.x;          // b*P + p
    const int b   = seq >> 7;
    const int p   = seq & (P - 1);
    const float2 a = g_Lbar[p];
    const int t = threadIdx.x;
    const int lane = t & 31, w = t >> 5;

    const float4* src = (const float4*)(g_Bu + (size_t)seq * LSEQ + t * 16);

    float2 x[16];
#pragma unroll
    for (int i = 0; i < 8; i++) {
        float4 v = src[i];
        x[2 * i]     = make_float2(v.x, v.y);
        x[2 * i + 1] = make_float2(v.z, v.w);
    }

    // local inclusive scan over 16 elems
    float2 v = make_float2(0.f, 0.f);
#pragma unroll
    for (int j = 0; j < 16; j++) {
        float2 av = cmul(a, v);
        v = make_float2(av.x + x[j].x, av.y + x[j].y);
        x[j] = v;
    }

    // a^16
    float2 a16 = cmul(a, a); a16 = cmul(a16, a16); a16 = cmul(a16, a16); a16 = cmul(a16, a16);

    // warp-level KS with growing factor
    float2 f = a16;
    float2 vi = v;
#pragma unroll
    for (int d = 1; d < 32; d <<= 1) {
        float px = __shfl_up_sync(0xffffffffu, vi.x, d);
        float py = __shfl_up_sync(0xffffffffu, vi.y, d);
        if (lane >= d) {
            float2 add = cmul(f, make_float2(px, py));
            vi.x += add.x; vi.y += add.y;
        }
        f = cmul(f, f);
    }
    // exclusive within warp
    float ex = __shfl_up_sync(0xffffffffu, vi.x, 1);
    float ey = __shfl_up_sync(0xffffffffu, vi.y, 1);
    float2 vex = (lane == 0) ? make_float2(0.f, 0.f) : make_float2(ex, ey);

    __shared__ float2 wsum[16];
    __shared__ float2 wpre[16];
    if (lane == 31) wsum[w] = vi;
    __syncthreads();

    // a^512
    float2 a512 = cmul(a16, a16); a512 = cmul(a512, a512); a512 = cmul(a512, a512);
    a512 = cmul(a512, a512); a512 = cmul(a512, a512);

    if (w == 0) {
        float2 s = (lane < 16) ? wsum[lane] : make_float2(0.f, 0.f);
        float2 g = a512;
#pragma unroll
        for (int d = 1; d < 16; d <<= 1) {
            float px = __shfl_up_sync(0xffffffffu, s.x, d);
            float py = __shfl_up_sync(0xffffffffu, s.y, d);
            if (lane >= d) {
                float2 add = cmul(g, make_float2(px, py));
                s.x += add.x; s.y += add.y;
            }
            g = cmul(g, g);
        }
        float qx = __shfl_up_sync(0xffffffffu, s.x, 1);
        float qy = __shfl_up_sync(0xffffffffu, s.y, 1);
        if (lane < 16) wpre[lane] = (lane == 0) ? make_float2(0.f, 0.f) : make_float2(qx, qy);
    }
    __syncthreads();

    // a^(16*lane) via binary exponentiation
    float2 pw16 = make_float2(1.f, 0.f);
    {
        float2 base = a16; int e = lane;
#pragma unroll
        for (int it = 0; it < 5; it++) {
            if (e & 1) pw16 = cmul(pw16, base);
            base = cmul(base, base);
            e >>= 1;
        }
    }
    float2 wc = wpre[w];
    float2 s0 = cmul(pw16, wc);
    s0.x += vex.x; s0.y += vex.y;          // state before this thread's chunk

    float2 pw = a;
#pragma unroll
    for (int j = 0; j < 16; j++) {
        float2 add = cmul(pw, s0);
        x[j].x += add.x; x[j].y += add.y;
        pw = cmul(pw, a);
    }

    // write split planes
    float* dre = g_X + ((size_t)(0 * BSZ + b) * P + p) * LSEQ + t * 16;
    float* dim = g_X + ((size_t)(1 * BSZ + b) * P + p) * LSEQ + t * 16;
    float re[16], im[16];
#pragma unroll
    for (int j = 0; j < 16; j++) { re[j] = x[j].x; im[j] = x[j].y; }
#pragma unroll
    for (int i = 0; i < 4; i++) {
        ((float4*)dre)[i] = make_float4(re[4*i], re[4*i+1], re[4*i+2], re[4*i+3]);
        ((float4*)dim)[i] = make_float4(im[4*i], im[4*i+1], im[4*i+2], im[4*i+3]);
    }
}

// ---------------------------------------------------------------------------
// K3: out[h,l] = gelu( sum_k A2T[k,h]*X[k,l] + D[h]*u[h,l] ).
// BM=128(h) BN=128(l) BK=16, 256 thr, 8x8 microtile, double-buffered cp.async.
// ---------------------------------------------------------------------------
__global__ void __launch_bounds__(256) out_gemm_kernel(const float* __restrict__ u,
                                                       const float* __restrict__ D,
                                                       float* __restrict__ out) {
    const int b  = blockIdx.z;
    const int n0 = blockIdx.x * 128;
    const int m0 = blockIdx.y * 128;
    const int tx = threadIdx.x & 15;   // n: tx*4, tx*4+64
    const int ty = threadIdx.x >> 4;   // m: ty*4, ty*4+64

    __shared__ __align__(16) float As[2][16][128];
    __shared__ __align__(16) float Bs[2][16][128];

    auto load_stage = [&](int buf, int k0) {
        int side = k0 >> 7;
        int pr0  = k0 & (P - 1);
        const float* xbase = g_X + ((size_t)(side * BSZ + b) * P) * LSEQ;
        for (int s = threadIdx.x; s < 512; s += 256) {
            int k = s >> 5, c = (s & 31) * 4;
            cp16(&As[buf][k][c], g_A2T + (size_t)(k0 + k) * H + m0 + c);
            cp16(&Bs[buf][k][c], xbase + (size_t)(pr0 + k) * LSEQ + n0 + c);
        }
        cp_commit();
    };

    float acc[8][8] = {};

    load_stage(0, 0);
    int buf = 0;
    for (int k0 = 0; k0 < 2 * P; k0 += 16) {
        cp_wait0();
        __syncthreads();
        if (k0 + 16 < 2 * P) load_stage(buf ^ 1, k0 + 16);

#pragma unroll
        for (int kk = 0; kk < 16; kk++) {
            float4 a0 = *(const float4*)&As[buf][kk][ty * 4];
            float4 a1 = *(const float4*)&As[buf][kk][ty * 4 + 64];
            float4 b0 = *(const float4*)&Bs[buf][kk][tx * 4];
            float4 b1 = *(const float4*)&Bs[buf][kk][tx * 4 + 64];
            float am[8] = {a0.x, a0.y, a0.z, a0.w, a1.x, a1.y, a1.z, a1.w};
            float bn[8] = {b0.x, b0.y, b0.z, b0.w, b1.x, b1.y, b1.z, b1.w};
#pragma unroll
            for (int m = 0; m < 8; m++)
#pragma unroll
                for (int n = 0; n < 8; n++) acc[m][n] += am[m] * bn[n];
        }
        __syncthreads();
        buf ^= 1;
    }

#pragma unroll
    for (int m = 0; m < 8; m++) {
        int h = m0 + ((m < 4) ? (ty * 4 + m) : (ty * 4 + 64 + m - 4));
        float dd = D[h];
        size_t rowb = (size_t)(b * H + h) * LSEQ + n0;
#pragma unroll
        for (int half = 0; half < 2; half++) {
            int n = tx * 4 + half * 64;
            float4 uv = *(const float4*)(u + rowb + n);
            float vals[4];
            vals[0] = acc[m][half * 4 + 0] + dd * uv.x;
            vals[1] = acc[m][half * 4 + 1] + dd * uv.y;
            vals[2] = acc[m][half * 4 + 2] + dd * uv.z;
            vals[3] = acc[m][half * 4 + 3] + dd * uv.w;
#pragma unroll
            for (int q = 0; q < 4; q++) {
                float xv = vals[q];
                vals[q] = 0.5f * xv * (1.0f + erff(xv * 0.70710678118654752f));
            }
            *(float4*)(out + rowb + n) = make_float4(vals[0], vals[1], vals[2], vals[3]);
        }
    }
}

// ---------------------------------------------------------------------------
extern "C" void kernel_launch(void* const* d_in, const int* in_sizes, int n_in,
                              void* d_out, int out_size) {
    const float* u   = (const float*)d_in[0];
    const float* Lre = (const float*)d_in[1];
    const float* Lim = (const float*)d_in[2];
    const float* Bm  = (const float*)d_in[3];
    const float* Cm  = (const float*)d_in[4];
    const float* D   = (const float*)d_in[5];
    const float* ls  = (const float*)d_in[6];
    float* out = (float*)d_out;

    setup_kernel<<<256, 256>>>(Lre, Lim, Bm, Cm, ls);

    dim3 g1(LSEQ / 64, 1, BSZ);
    bu_gemm_kernel<<<g1, 256>>>(u);

    scan_kernel<<<BSZ * P, 512>>>();

    dim3 g3(LSEQ / 128, H / 128, BSZ);
    out_gemm_kernel<<<g3, 256>>>(u, D, out);
}

// round 9
// speedup vs baseline: 2.1216x; 2.1216x over previous
#include <cuda_runtime.h>
#include <cuda_bf16.h>
#include <stdint.h>
#include <math.h>

#define BSZ  8
#define H    512
#define P    128
#define LSEQ 8192
#define K2   256          // 2P

// ---------------- scratch (__device__ globals; allocation-free rule) --------
__device__ __nv_bfloat16 g_uThi[(size_t)BSZ * LSEQ * H];   // u transposed [b][l][h], hi
__device__ __nv_bfloat16 g_uTlo[(size_t)BSZ * LSEQ * H];   // lo
__device__ __nv_bfloat16 g_xThi[(size_t)BSZ * LSEQ * K2];  // xs transposed [b][l][2p]
__device__ __nv_bfloat16 g_xTlo[(size_t)BSZ * LSEQ * K2];
__device__ float g_Sre[(size_t)BSZ * P * LSEQ];            // Bu / xs re plane [b*P+p][l]
__device__ float g_Sim[(size_t)BSZ * P * LSEQ];            // im plane
__device__ __nv_bfloat16 g_Bsthi[K2 * H];                  // stacked Bbar: row p = re, row 128+p = im
__device__ __nv_bfloat16 g_Bstlo[K2 * H];
__device__ __nv_bfloat16 g_C2hi[H * K2];                   // folded C: [h][k], k<128: 2*Cre else -2*Cim
__device__ __nv_bfloat16 g_C2lo[H * K2];
__device__ float2 g_Lbar[P];

// ---------------- helpers ---------------------------------------------------
__device__ __forceinline__ float2 cmul(float2 a, float2 b) {
    return make_float2(a.x * b.x - a.y * b.y, a.x * b.y + a.y * b.x);
}
__device__ __forceinline__ void bf16split(float v, __nv_bfloat16& hi, __nv_bfloat16& lo) {
    hi = __float2bfloat16(v);
    lo = __float2bfloat16(v - __bfloat162float(hi));
}
__device__ __forceinline__ unsigned smem_u32(const void* p) {
    return (unsigned)__cvta_generic_to_shared(p);
}
__device__ __forceinline__ void cp16(unsigned s, const void* g) {
    asm volatile("cp.async.cg.shared.global [%0], [%1], 16;\n" :: "r"(s), "l"(g));
}
__device__ __forceinline__ void cp_commit() { asm volatile("cp.async.commit_group;\n"); }
__device__ __forceinline__ void cp_wait0()  { asm volatile("cp.async.wait_group 0;\n"); }
__device__ __forceinline__ void cp_wait1()  { asm volatile("cp.async.wait_group 1;\n"); }

#define LDSM_X4(r0, r1, r2, r3, a)                                              \
    asm volatile("ldmatrix.sync.aligned.m8n8.x4.shared.b16 {%0,%1,%2,%3}, [%4];"\
                 : "=r"(r0), "=r"(r1), "=r"(r2), "=r"(r3) : "r"(a))

#define MMA16816(c, a, b)                                                       \
    asm volatile("mma.sync.aligned.m16n8k16.row.col.f32.bf16.bf16.f32 "         \
                 "{%0,%1,%2,%3}, {%4,%5,%6,%7}, {%8,%9}, {%0,%1,%2,%3};"        \
                 : "+f"((c)[0]), "+f"((c)[1]), "+f"((c)[2]), "+f"((c)[3])       \
                 : "r"((a)[0]), "r"((a)[1]), "r"((a)[2]), "r"((a)[3]),          \
                   "r"((b)[0]), "r"((b)[1]))

// Stage layout: Ahi | Alo | Bhi | Blo, each 128 rows x 32 bf16, row stride 80 B
#define ROWB      80
#define MATB      10240                 // 128 * 80
#define STAGEB    40960                 // 4 * MATB
#define SMEM_DYN  81920                 // 2 stages; C-transpose (67584 B) overlaps

// ---------------------------------------------------------------------------
// Setup: Lambda_bar, stacked split Bbar [2p][h], folded split C [h][2p].
// ---------------------------------------------------------------------------
__global__ void setup_kernel(const float* __restrict__ Lre, const float* __restrict__ Lim,
                             const float* __restrict__ Bm, const float* __restrict__ Cm,
                             const float* __restrict__ logstep) {
    int tid = blockIdx.x * blockDim.x + threadIdx.x;
    int stride = gridDim.x * blockDim.x;

    if (tid < P) {
        double st = exp((double)logstep[tid]);
        double zre = (double)Lre[tid] * st, zim = (double)Lim[tid] * st;
        double er = exp(zre);
        g_Lbar[tid] = make_float2((float)(er * cos(zim)), (float)(er * sin(zim)));
    }

    for (int i = tid; i < P * H; i += stride) {
        int p = i >> 9, h = i & (H - 1);
        double st  = exp((double)logstep[p]);
        double lre = (double)Lre[p], lim = (double)Lim[p];
        double zre = lre * st, zim = lim * st;
        double er  = exp(zre);
        double numr = er * cos(zim) - 1.0;
        double numi = er * sin(zim);
        double den  = lre * lre + lim * lim;
        double gre = (numr * lre + numi * lim) / den;
        double gim = (numi * lre - numr * lim) / den;
        float br = Bm[2 * i], bi = Bm[2 * i + 1];
        float vre = (float)(gre * (double)br - gim * (double)bi);
        float vim = (float)(gre * (double)bi + gim * (double)br);
        __nv_bfloat16 hi, lo;
        bf16split(vre, hi, lo);
        g_Bsthi[p * H + h] = hi; g_Bstlo[p * H + h] = lo;
        bf16split(vim, hi, lo);
        g_Bsthi[(P + p) * H + h] = hi; g_Bstlo[(P + p) * H + h] = lo;
    }

    for (int i = tid; i < H * K2; i += stride) {
        int h = i >> 8, k = i & (K2 - 1);
        float v = (k < P) ? 2.0f * Cm[(h * P + k) * 2]
                          : -2.0f * Cm[(h * P + (k - P)) * 2 + 1];
        __nv_bfloat16 hi, lo;
        bf16split(v, hi, lo);
        g_C2hi[(size_t)h * K2 + k] = hi;
        g_C2lo[(size_t)h * K2 + k] = lo;
    }
}

// ---------------------------------------------------------------------------
// Transpose+split u: [b][h][l] fp32 -> [b][l][h] bf16 hi/lo. 64x64 tiles.
// ---------------------------------------------------------------------------
__global__ void __launch_bounds__(256) transpose_u_kernel(const float* __restrict__ u) {
    __shared__ float tile[64][65];
    const int b  = blockIdx.z;
    const int h0 = blockIdx.y * 64;
    const int l0 = blockIdx.x * 64;

    for (int idx = threadIdx.x; idx < 64 * 64; idx += 256) {
        int i = idx >> 6, j = idx & 63;
        tile[i][j] = u[((size_t)b * H + h0 + i) * LSEQ + l0 + j];
    }
    __syncthreads();
    for (int idx = threadIdx.x; idx < 64 * 32; idx += 256) {
        int j = idx >> 5, ip = (idx & 31) * 2;
        float v0 = tile[ip][j], v1 = tile[ip + 1][j];
        __nv_bfloat16 h0b, l0b, h1b, l1b;
        bf16split(v0, h0b, l0b);
        bf16split(v1, h1b, l1b);
        size_t o = ((size_t)b * LSEQ + l0 + j) * H + h0 + ip;
        *(__nv_bfloat162*)&g_uThi[o] = __nv_bfloat162{h0b, h1b};
        *(__nv_bfloat162*)&g_uTlo[o] = __nv_bfloat162{l0b, l1b};
    }
}

// ---------------------------------------------------------------------------
// Transpose+split xs planes -> [b][l][side*128+p] bf16 hi/lo.
// ---------------------------------------------------------------------------
__global__ void __launch_bounds__(256) transpose_x_kernel() {
    __shared__ float tile[128][65];
    const int by   = blockIdx.y;          // 0..15
    const int side = by & 1;
    const int b    = by >> 1;
    const int l0   = blockIdx.x * 64;
    const float* src = side ? g_Sim : g_Sre;

    for (int idx = threadIdx.x; idx < 128 * 64; idx += 256) {
        int i = idx >> 6, j = idx & 63;
        tile[i][j] = src[(size_t)(b * P + i) * LSEQ + l0 + j];
    }
    __syncthreads();
    for (int idx = threadIdx.x; idx < 64 * 64; idx += 256) {
        int j = idx >> 6, ip = (idx & 63) * 2;
        float v0 = tile[ip][j], v1 = tile[ip + 1][j];
        __nv_bfloat16 h0b, l0b, h1b, l1b;
        bf16split(v0, h0b, l0b);
        bf16split(v1, h1b, l1b);
        size_t o = ((size_t)b * LSEQ + l0 + j) * K2 + side * P + ip;
        *(__nv_bfloat162*)&g_xThi[o] = __nv_bfloat162{h0b, h1b};
        *(__nv_bfloat162*)&g_xTlo[o] = __nv_bfloat162{l0b, l1b};
    }
}

// ---------------------------------------------------------------------------
// Shared MMA mainloop: C[128l x 128n] += A[128 x K] * B[128 x K]^T, both
// K-major bf16 hi/lo, 3-term split. KDIM in {512, 256}. Double-buffered.
// ---------------------------------------------------------------------------
template <int KDIM>
__device__ __forceinline__ void mma_mainloop(
    const __nv_bfloat16* __restrict__ Ahi, const __nv_bfloat16* __restrict__ Alo,
    const __nv_bfloat16* __restrict__ Bhi, const __nv_bfloat16* __restrict__ Blo,
    unsigned sbase, int tid, int wid, int lane, float c[4][4][4])
{
    const int m0w = (wid >> 2) * 64;
    const int n0w = (wid & 3) * 32;
    constexpr int NCH = KDIM / 32;

    auto load_stage = [&](int buf, int k0) {
#pragma unroll
        for (int i = 0; i < 8; i++) {
            int idx = tid + i * 256;           // 0..2047
            int mat = idx >> 9;                // uniform per i
            int r   = (idx >> 2) & 127;
            int seg = idx & 3;
            unsigned dst = sbase + buf * STAGEB + mat * MATB + r * ROWB + seg * 16;
            const __nv_bfloat16* src =
                (mat == 0) ? (Ahi + (size_t)r * KDIM + k0 + seg * 8) :
                (mat == 1) ? (Alo + (size_t)r * KDIM + k0 + seg * 8) :
                (mat == 2) ? (Bhi + (size_t)r * KDIM + k0 + seg * 8) :
                             (Blo + (size_t)r * KDIM + k0 + seg * 8);
            cp16(dst, src);
        }
        cp_commit();
    };

    load_stage(0, 0);
    load_stage(1, 32);

    for (int ch = 0; ch < NCH; ch++) {
        if (ch < NCH - 1) cp_wait1(); else cp_wait0();
        __syncthreads();

        const unsigned sb = sbase + (ch & 1) * STAGEB;
#pragma unroll
        for (int ks = 0; ks < 2; ks++) {
            const unsigned koff = ks * 32 + (lane >> 4) * 16;   // bytes within row
            unsigned aH[4][4], aL[4][4], bH[4][2], bL[4][2];
#pragma unroll
            for (int mt = 0; mt < 4; mt++) {
                unsigned ra = sb + (m0w + mt * 16 + (lane & 15)) * ROWB + koff;
                LDSM_X4(aH[mt][0], aH[mt][1], aH[mt][2], aH[mt][3], ra);
                LDSM_X4(aL[mt][0], aL[mt][1], aL[mt][2], aL[mt][3], ra + MATB);
            }
#pragma unroll
            for (int np = 0; np < 2; np++) {
                unsigned rb = sb + 2 * MATB + (n0w + np * 16 + (lane & 15)) * ROWB + koff;
                unsigned t0, t1, t2, t3;
                LDSM_X4(t0, t1, t2, t3, rb);
                bH[np * 2 + 0][0] = t0; bH[np * 2 + 0][1] = t2;
                bH[np * 2 + 1][0] = t1; bH[np * 2 + 1][1] = t3;
                LDSM_X4(t0, t1, t2, t3, rb + MATB);
                bL[np * 2 + 0][0] = t0; bL[np * 2 + 0][1] = t2;
                bL[np * 2 + 1][0] = t1; bL[np * 2 + 1][1] = t3;
            }
#pragma unroll
            for (int mt = 0; mt < 4; mt++)
#pragma unroll
                for (int nt = 0; nt < 4; nt++) {
                    MMA16816(c[mt][nt], aH[mt], bH[nt]);
                    MMA16816(c[mt][nt], aL[mt], bH[nt]);
                    MMA16816(c[mt][nt], aH[mt], bL[nt]);
                }
        }
        __syncthreads();
        if (ch + 2 < NCH) load_stage(ch & 1, (ch + 2) * 32);
    }
}

// Store C frags to smem transposed as Cs[n][l] (stride 132, conflict-free).
__device__ __forceinline__ void stage_c_transposed(float* cs, int wid, int lane,
                                                   float c[4][4][4]) {
    const int m0w = (wid >> 2) * 64;
    const int n0w = (wid & 3) * 32;
#pragma unroll
    for (int mt = 0; mt < 4; mt++)
#pragma unroll
        for (int nt = 0; nt < 4; nt++) {
            int r0 = m0w + mt * 16 + (lane >> 2);
            int cb = n0w + nt * 8 + (lane & 3) * 2;
            cs[cb * 132 + r0]           = c[mt][nt][0];
            cs[(cb + 1) * 132 + r0]     = c[mt][nt][1];
            cs[cb * 132 + r0 + 8]       = c[mt][nt][2];
            cs[(cb + 1) * 132 + r0 + 8] = c[mt][nt][3];
        }
}

// ---------------------------------------------------------------------------
// K1: Bu planes. blockIdx: x = l-tile, y = plane (0 re, 1 im), z = batch.
// ---------------------------------------------------------------------------
__global__ void __launch_bounds__(256, 1) bu_mma_kernel() {
    extern __shared__ __align__(16) char dsm[];
    const unsigned sbase = smem_u32(dsm);
    const int b  = blockIdx.z;
    const int l0 = blockIdx.x * 128;
    const int n0g = blockIdx.y * 128;
    const int tid = threadIdx.x, wid = tid >> 5, lane = tid & 31;

    float c[4][4][4] = {};
    mma_mainloop<H>(g_uThi + ((size_t)b * LSEQ + l0) * H,
                    g_uTlo + ((size_t)b * LSEQ + l0) * H,
                    g_Bsthi + (size_t)n0g * H,
                    g_Bstlo + (size_t)n0g * H,
                    sbase, tid, wid, lane, c);

    float* cs = (float*)dsm;
    stage_c_transposed(cs, wid, lane, c);
    __syncthreads();

    float* plane = blockIdx.y ? g_Sim : g_Sre;
#pragma unroll
    for (int i = 0; i < 16; i++) {
        int n = wid * 16 + i;                  // p
        float4 v = *(float4*)&cs[n * 132 + lane * 4];
        *(float4*)&plane[(size_t)(b * P + n) * LSEQ + l0 + lane * 4] = v;
    }
}

// ---------------------------------------------------------------------------
// K3: out. blockIdx: x = l-tile, y = h-block (4), z = batch. Fused D*u + gelu.
// ---------------------------------------------------------------------------
__global__ void __launch_bounds__(256, 1) out_mma_kernel(const float* __restrict__ u,
                                                         const float* __restrict__ Dv,
                                                         float* __restrict__ out) {
    extern __shared__ __align__(16) char dsm[];
    const unsigned sbase = smem_u32(dsm);
    const int b  = blockIdx.z;
    const int l0 = blockIdx.x * 128;
    const int h0 = blockIdx.y * 128;
    const int tid = threadIdx.x, wid = tid >> 5, lane = tid & 31;

    float c[4][4][4] = {};
    mma_mainloop<K2>(g_xThi + ((size_t)b * LSEQ + l0) * K2,
                     g_xTlo + ((size_t)b * LSEQ + l0) * K2,
                     g_C2hi + (size_t)h0 * K2,
                     g_C2lo + (size_t)h0 * K2,
                     sbase, tid, wid, lane, c);

    float* cs = (float*)dsm;
    stage_c_transposed(cs, wid, lane, c);
    __syncthreads();

#pragma unroll
    for (int i = 0; i < 16; i++) {
        int n = wid * 16 + i;
        int h = h0 + n;
        float4 v = *(float4*)&cs[n * 132 + lane * 4];
        size_t o = (size_t)(b * H + h) * LSEQ + l0 + lane * 4;
        float4 uv = *(const float4*)&u[o];
        float dd = Dv[h];
        float r[4] = {v.x + dd * uv.x, v.y + dd * uv.y, v.z + dd * uv.z, v.w + dd * uv.w};
#pragma unroll
        for (int q = 0; q < 4; q++)
            r[q] = 0.5f * r[q] * (1.0f + erff(r[q] * 0.70710678118654752f));
        *(float4*)&out[o] = make_float4(r[0], r[1], r[2], r[3]);
    }
}

// ---------------------------------------------------------------------------
// Scan along L per (b,p); warp-shuffle Kogge-Stone; split planes in place.
// ---------------------------------------------------------------------------
__global__ void __launch_bounds__(512) scan_kernel() {
    const int seq = blockIdx.x;          // b*P + p
    const int p   = seq & (P - 1);
    const float2 a = g_Lbar[p];
    const int t = threadIdx.x;
    const int lane = t & 31, w = t >> 5;

    float4* rre = (float4*)(g_Sre + (size_t)seq * LSEQ + t * 16);
    float4* rim = (float4*)(g_Sim + (size_t)seq * LSEQ + t * 16);

    float2 x[16];
#pragma unroll
    for (int i = 0; i < 4; i++) {
        float4 vr = rre[i], vi = rim[i];
        x[4 * i + 0] = make_float2(vr.x, vi.x);
        x[4 * i + 1] = make_float2(vr.y, vi.y);
        x[4 * i + 2] = make_float2(vr.z, vi.z);
        x[4 * i + 3] = make_float2(vr.w, vi.w);
    }

    float2 v = make_float2(0.f, 0.f);
#pragma unroll
    for (int j = 0; j < 16; j++) {
        float2 av = cmul(a, v);
        v = make_float2(av.x + x[j].x, av.y + x[j].y);
        x[j] = v;
    }

    float2 a16 = cmul(a, a); a16 = cmul(a16, a16); a16 = cmul(a16, a16); a16 = cmul(a16, a16);

    float2 f = a16;
    float2 vi2 = v;
#pragma unroll
    for (int d = 1; d < 32; d <<= 1) {
        float px = __shfl_up_sync(0xffffffffu, vi2.x, d);
        float py = __shfl_up_sync(0xffffffffu, vi2.y, d);
        if (lane >= d) {
            float2 add = cmul(f, make_float2(px, py));
            vi2.x += add.x; vi2.y += add.y;
        }
        f = cmul(f, f);
    }
    float ex = __shfl_up_sync(0xffffffffu, vi2.x, 1);
    float ey = __shfl_up_sync(0xffffffffu, vi2.y, 1);
    float2 vex = (lane == 0) ? make_float2(0.f, 0.f) : make_float2(ex, ey);

    __shared__ float2 wsum[16];
    __shared__ float2 wpre[16];
    if (lane == 31) wsum[w] = vi2;
    __syncthreads();

    float2 a512 = cmul(a16, a16); a512 = cmul(a512, a512); a512 = cmul(a512, a512);
    a512 = cmul(a512, a512); a512 = cmul(a512, a512);

    if (w == 0) {
        float2 s = (lane < 16) ? wsum[lane] : make_float2(0.f, 0.f);
        float2 g = a512;
#pragma unroll
        for (int d = 1; d < 16; d <<= 1) {
            float px = __shfl_up_sync(0xffffffffu, s.x, d);
            float py = __shfl_up_sync(0xffffffffu, s.y, d);
            if (lane >= d) {
                float2 add = cmul(g, make_float2(px, py));
                s.x += add.x; s.y += add.y;
            }
            g = cmul(g, g);
        }
        float qx = __shfl_up_sync(0xffffffffu, s.x, 1);
        float qy = __shfl_up_sync(0xffffffffu, s.y, 1);
        if (lane < 16) wpre[lane] = (lane == 0) ? make_float2(0.f, 0.f) : make_float2(qx, qy);
    }
    __syncthreads();

    float2 pw16 = make_float2(1.f, 0.f);
    {
        float2 base = a16; int e = lane;
#pragma unroll
        for (int it = 0; it < 5; it++) {
            if (e & 1) pw16 = cmul(pw16, base);
            base = cmul(base, base);
            e >>= 1;
        }
    }
    float2 wc = wpre[w];
    float2 s0 = cmul(pw16, wc);
    s0.x += vex.x; s0.y += vex.y;

    float2 pw = a;
#pragma unroll
    for (int j = 0; j < 16; j++) {
        float2 add = cmul(pw, s0);
        x[j].x += add.x; x[j].y += add.y;
        pw = cmul(pw, a);
    }

#pragma unroll
    for (int i = 0; i < 4; i++) {
        rre[i] = make_float4(x[4*i].x, x[4*i+1].x, x[4*i+2].x, x[4*i+3].x);
        rim[i] = make_float4(x[4*i].y, x[4*i+1].y, x[4*i+2].y, x[4*i+3].y);
    }
}

// ---------------------------------------------------------------------------
extern "C" void kernel_launch(void* const* d_in, const int* in_sizes, int n_in,
                              void* d_out, int out_size) {
    const float* u   = (const float*)d_in[0];
    const float* Lre = (const float*)d_in[1];
    const float* Lim = (const float*)d_in[2];
    const float* Bm  = (const float*)d_in[3];
    const float* Cm  = (const float*)d_in[4];
    const float* D   = (const float*)d_in[5];
    const float* ls  = (const float*)d_in[6];
    float* out = (float*)d_out;

    cudaFuncSetAttribute(bu_mma_kernel,  cudaFuncAttributeMaxDynamicSharedMemorySize, SMEM_DYN);
    cudaFuncSetAttribute(out_mma_kernel, cudaFuncAttributeMaxDynamicSharedMemorySize, SMEM_DYN);

    setup_kernel<<<256, 256>>>(Lre, Lim, Bm, Cm, ls);

    transpose_u_kernel<<<dim3(LSEQ / 64, H / 64, BSZ), 256>>>(u);

    bu_mma_kernel<<<dim3(LSEQ / 128, 2, BSZ), 256, SMEM_DYN>>>();

    scan_kernel<<<BSZ * P, 512>>>();

    transpose_x_kernel<<<dim3(LSEQ / 64, 2 * BSZ, 1), 256>>>();

    out_mma_kernel<<<dim3(LSEQ / 128, 4, BSZ), 256, SMEM_DYN>>>(u, D, out);
}

// round 10
// speedup vs baseline: 3.2048x; 1.5106x over previous
#include <cuda_runtime.h>
#include <cuda_fp16.h>
#include <stdint.h>
#include <math.h>

#define BSZ  8
#define H    512
#define P    128
#define LSEQ 8192
#define K2   256          // 2P

// ---------------- scratch (__device__ globals; allocation-free rule) --------
__device__ __align__(16) __half g_uH[(size_t)BSZ * H * LSEQ];   // u fp16 [b][h][l]
__device__ __align__(16) float  g_S [(size_t)BSZ * K2 * LSEQ];  // Bu fp32 [b][2p][l] (re 0-127, im 128-255)
__device__ __align__(16) __half g_Xh[(size_t)BSZ * K2 * LSEQ];  // xs fp16 [b][2p][l]
__device__ __align__(16) __half g_Wh[K2 * H];                   // Bst hi [2p][h] (K-major h)
__device__ __align__(16) __half g_Wl[K2 * H];                   // Bst lo
__device__ __align__(16) __half g_Ch[H * K2];                   // folded C hi [h][2p]
__device__ __align__(16) __half g_Cl[H * K2];                   // folded C lo
__device__ float2 g_Lbar[P];

// ---------------- helpers ---------------------------------------------------
__device__ __forceinline__ float2 cmul(float2 a, float2 b) {
    return make_float2(a.x * b.x - a.y * b.y, a.x * b.y + a.y * b.x);
}
__device__ __forceinline__ void h16split(float v, __half& hi, __half& lo) {
    hi = __float2half_rn(v);
    lo = __float2half_rn(v - __half2float(hi));
}
__device__ __forceinline__ unsigned smem_u32(const void* p) {
    return (unsigned)__cvta_generic_to_shared(p);
}
__device__ __forceinline__ void cp16(unsigned s, const void* g) {
    asm volatile("cp.async.cg.shared.global [%0], [%1], 16;\n" :: "r"(s), "l"(g));
}
__device__ __forceinline__ void cp_commit() { asm volatile("cp.async.commit_group;\n"); }
__device__ __forceinline__ void cp_wait0()  { asm volatile("cp.async.wait_group 0;\n"); }
__device__ __forceinline__ void cp_wait1()  { asm volatile("cp.async.wait_group 1;\n"); }

#define LDSM_X4(r0, r1, r2, r3, a)                                              \
    asm volatile("ldmatrix.sync.aligned.m8n8.x4.shared.b16 {%0,%1,%2,%3}, [%4];"\
                 : "=r"(r0), "=r"(r1), "=r"(r2), "=r"(r3) : "r"(a))
#define LDSM_X4_T(r0, r1, r2, r3, a)                                            \
    asm volatile("ldmatrix.sync.aligned.m8n8.x4.trans.shared.b16 {%0,%1,%2,%3}, [%4];"\
                 : "=r"(r0), "=r"(r1), "=r"(r2), "=r"(r3) : "r"(a))

#define MMA16816(c, a, b)                                                       \
    asm volatile("mma.sync.aligned.m16n8k16.row.col.f32.f16.f16.f32 "           \
                 "{%0,%1,%2,%3}, {%4,%5,%6,%7}, {%8,%9}, {%0,%1,%2,%3};"        \
                 : "+f"((c)[0]), "+f"((c)[1]), "+f"((c)[2]), "+f"((c)[3])       \
                 : "r"((a)[0]), "r"((a)[1]), "r"((a)[2]), "r"((a)[3]),          \
                   "r"((b)[0]), "r"((b)[1]))

// A rows: 32 halfs = 64B + 16B pad = 80B stride (conflict-free ldmatrix)
// B tile: 32 k-rows x 136 halfs = 272B stride (conflict-free trans ldmatrix)

// ---------------------------------------------------------------------------
// Setup: Lambda_bar, fp16-split stacked Bbar [2p][h], fp16-split folded C [h][2p].
// ---------------------------------------------------------------------------
__global__ void setup_kernel(const float* __restrict__ Lre, const float* __restrict__ Lim,
                             const float* __restrict__ Bm, const float* __restrict__ Cm,
                             const float* __restrict__ logstep) {
    int tid = blockIdx.x * blockDim.x + threadIdx.x;
    int stride = gridDim.x * blockDim.x;

    if (tid < P) {
        double st = exp((double)logstep[tid]);
        double zre = (double)Lre[tid] * st, zim = (double)Lim[tid] * st;
        double er = exp(zre);
        g_Lbar[tid] = make_float2((float)(er * cos(zim)), (float)(er * sin(zim)));
    }

    for (int i = tid; i < P * H; i += stride) {
        int p = i >> 9, h = i & (H - 1);
        double st  = exp((double)logstep[p]);
        double lre = (double)Lre[p], lim = (double)Lim[p];
        double zre = lre * st, zim = lim * st;
        double er  = exp(zre);
        double numr = er * cos(zim) - 1.0;
        double numi = er * sin(zim);
        double den  = lre * lre + lim * lim;
        double gre = (numr * lre + numi * lim) / den;
        double gim = (numi * lre - numr * lim) / den;
        float br = Bm[2 * i], bi = Bm[2 * i + 1];
        float vre = (float)(gre * (double)br - gim * (double)bi);
        float vim = (float)(gre * (double)bi + gim * (double)br);
        __half hi, lo;
        h16split(vre, hi, lo);
        g_Wh[p * H + h] = hi; g_Wl[p * H + h] = lo;
        h16split(vim, hi, lo);
        g_Wh[(P + p) * H + h] = hi; g_Wl[(P + p) * H + h] = lo;
    }

    for (int i = tid; i < H * K2; i += stride) {
        int h = i >> 8, k = i & (K2 - 1);
        float v = (k < P) ? 2.0f * Cm[(h * P + k) * 2]
                          : -2.0f * Cm[(h * P + (k - P)) * 2 + 1];
        __half hi, lo;
        h16split(v, hi, lo);
        g_Ch[(size_t)h * K2 + k] = hi;
        g_Cl[(size_t)h * K2 + k] = lo;
    }
}

// ---------------------------------------------------------------------------
// u fp32 -> fp16, same layout (elementwise, fully coalesced).
// ---------------------------------------------------------------------------
__global__ void __launch_bounds__(256) uconv_kernel(const float* __restrict__ u) {
    size_t i = ((size_t)blockIdx.x * 256 + threadIdx.x) * 8;
    float4 a = *(const float4*)(u + i);
    float4 b = *(const float4*)(u + i + 4);
    __half2 h[4];
    h[0] = __floats2half2_rn(a.x, a.y);
    h[1] = __floats2half2_rn(a.z, a.w);
    h[2] = __floats2half2_rn(b.x, b.y);
    h[3] = __floats2half2_rn(b.z, b.w);
    *(uint4*)(g_uH + i) = *(uint4*)h;
}

// ---------------------------------------------------------------------------
// Shared MMA mainloop: C[MROWS x 128] = W(hi+lo)[MROWS x KD] * Bg[KD x 128],
// W K-major fp16 hi/lo (2 MMA terms), Bg natural [k][L] via ldmatrix.trans.
// 8 warps as 4(m) x 2(n); warp tile (MT*16) x 64. Double-buffered cp.async.
// ---------------------------------------------------------------------------
template <int KD, int MROWS, int MT>
__device__ __forceinline__ void mma_mainloop(
    const __half* __restrict__ Wh, const __half* __restrict__ Wl,
    const __half* __restrict__ Bg, int l0,
    unsigned sbase, int tid, int wid, int lane, float c[MT][8][4])
{
    constexpr int AB   = MROWS * 80;
    constexpr int BOFF = 2 * AB;
    constexpr int STG  = BOFF + 32 * 272;
    const int wr = wid >> 1, wc = wid & 1;
    const int m0w = wr * (MT * 16);
    const int n0w = wc * 64;
    constexpr int NCH = KD / 32;

    auto load_stage = [&](int buf, int k0) {
        unsigned sb = sbase + buf * STG;
        for (int s = tid; s < MROWS * 4; s += 256) {
            int r = s >> 2, seg = s & 3;
            cp16(sb + r * 80 + seg * 16, Wh + (size_t)r * KD + k0 + seg * 8);
            cp16(sb + AB + r * 80 + seg * 16, Wl + (size_t)r * KD + k0 + seg * 8);
        }
        for (int s = tid; s < 512; s += 256) {
            int r = s >> 4, seg = s & 15;
            cp16(sb + BOFF + r * 272 + seg * 16,
                 Bg + (size_t)(k0 + r) * LSEQ + l0 + seg * 8);
        }
        cp_commit();
    };

    load_stage(0, 0);
    load_stage(1, 32);

    for (int ch = 0; ch < NCH; ch++) {
        if (ch < NCH - 1) cp_wait1(); else cp_wait0();
        __syncthreads();
        unsigned sb = sbase + (ch & 1) * STG;

#pragma unroll
        for (int ks = 0; ks < 2; ks++) {
            unsigned aH[MT][4], aL[MT][4];
            unsigned koff = ks * 32 + (lane >> 4) * 16;
#pragma unroll
            for (int mt = 0; mt < MT; mt++) {
                unsigned ra = sb + (m0w + mt * 16 + (lane & 15)) * 80 + koff;
                LDSM_X4(aH[mt][0], aH[mt][1], aH[mt][2], aH[mt][3], ra);
                LDSM_X4(aL[mt][0], aL[mt][1], aL[mt][2], aL[mt][3], ra + AB);
            }
            unsigned b[8][2];
#pragma unroll
            for (int np = 0; np < 4; np++) {
                unsigned rb = sb + BOFF + (ks * 16 + (lane & 15)) * 272
                            + (n0w + np * 16 + (lane >> 4) * 8) * 2;
                unsigned t0, t1, t2, t3;
                LDSM_X4_T(t0, t1, t2, t3, rb);
                b[2 * np][0]     = t0; b[2 * np][1]     = t1;
                b[2 * np + 1][0] = t2; b[2 * np + 1][1] = t3;
            }
#pragma unroll
            for (int mt = 0; mt < MT; mt++)
#pragma unroll
                for (int nt = 0; nt < 8; nt++) {
                    MMA16816(c[mt][nt], aH[mt], b[nt]);
                    MMA16816(c[mt][nt], aL[mt], b[nt]);
                }
        }
        __syncthreads();
        if (ch + 2 < NCH) load_stage(ch & 1, (ch + 2) * 32);
    }
}

#define SMEM_K1 (2 * (2 * 256 * 80 + 32 * 272))   // 99328
#define SMEM_K3 (2 * (2 * 128 * 80 + 32 * 272))   // 58368

// ---------------------------------------------------------------------------
// K1: Bu planes. C[2p(256) x l(128)] = Bst * u. Direct plane writes.
// ---------------------------------------------------------------------------
__global__ void __launch_bounds__(256, 1) bu_mma_kernel() {
    extern __shared__ __align__(16) char dsm[];
    const unsigned sbase = smem_u32(dsm);
    const int b = blockIdx.z, l0 = blockIdx.x * 128;
    const int tid = threadIdx.x, wid = tid >> 5, lane = tid & 31;

    float c[4][8][4] = {};
    mma_mainloop<H, 256, 4>(g_Wh, g_Wl, g_uH + (size_t)b * H * LSEQ,
                            l0, sbase, tid, wid, lane, c);

    const int wr = wid >> 1, wc = wid & 1;
    const int m0w = wr * 64, n0w = wc * 64;
#pragma unroll
    for (int mt = 0; mt < 4; mt++)
#pragma unroll
        for (int nt = 0; nt < 8; nt++) {
            int row = m0w + mt * 16 + (lane >> 2);
            int col = n0w + nt * 8 + (lane & 3) * 2;
            float* dst = g_S + ((size_t)b * K2 + row) * LSEQ + l0 + col;
            *(float2*)dst = make_float2(c[mt][nt][0], c[mt][nt][1]);
            *(float2*)(dst + (size_t)8 * LSEQ) = make_float2(c[mt][nt][2], c[mt][nt][3]);
        }
}

// ---------------------------------------------------------------------------
// K3: out. C[h(128) x l(128)] = C2 * xs; epilogue + D*u + exact gelu.
// ---------------------------------------------------------------------------
__global__ void __launch_bounds__(256, 1) out_mma_kernel(const float* __restrict__ u,
                                                         const float* __restrict__ Dv,
                                                         float* __restrict__ out) {
    extern __shared__ __align__(16) char dsm[];
    const unsigned sbase = smem_u32(dsm);
    const int b = blockIdx.z, l0 = blockIdx.x * 128, h0 = blockIdx.y * 128;
    const int tid = threadIdx.x, wid = tid >> 5, lane = tid & 31;

    float c[2][8][4] = {};
    mma_mainloop<K2, 128, 2>(g_Ch + (size_t)h0 * K2, g_Cl + (size_t)h0 * K2,
                             g_Xh + (size_t)b * K2 * LSEQ,
                             l0, sbase, tid, wid, lane, c);

    const int wr = wid >> 1, wc = wid & 1;
    const int m0w = wr * 32, n0w = wc * 64;
#pragma unroll
    for (int mt = 0; mt < 2; mt++)
#pragma unroll
        for (int nt = 0; nt < 8; nt++) {
            int row = m0w + mt * 16 + (lane >> 2);
            int col = n0w + nt * 8 + (lane & 3) * 2;
            int h = h0 + row;
            size_t o = ((size_t)b * H + h) * LSEQ + l0 + col;

            float2 uv = *(const float2*)(u + o);
            float dd = Dv[h];
            float v0 = c[mt][nt][0] + dd * uv.x;
            float v1 = c[mt][nt][1] + dd * uv.y;
            v0 = 0.5f * v0 * (1.0f + erff(v0 * 0.70710678118654752f));
            v1 = 0.5f * v1 * (1.0f + erff(v1 * 0.70710678118654752f));
            *(float2*)(out + o) = make_float2(v0, v1);

            size_t o2 = o + (size_t)8 * LSEQ;
            float2 uw = *(const float2*)(u + o2);
            float de = Dv[h + 8];
            float v2 = c[mt][nt][2] + de * uw.x;
            float v3 = c[mt][nt][3] + de * uw.y;
            v2 = 0.5f * v2 * (1.0f + erff(v2 * 0.70710678118654752f));
            v3 = 0.5f * v3 * (1.0f + erff(v3 * 0.70710678118654752f));
            *(float2*)(out + o2) = make_float2(v2, v3);
        }
}

// ---------------------------------------------------------------------------
// Scan along L per (b,p); warp-shuffle Kogge-Stone; fp32 in, fp16 planes out.
// ---------------------------------------------------------------------------
__global__ void __launch_bounds__(512) scan_kernel() {
    const int seq = blockIdx.x;          // b*P + p
    const int b   = seq >> 7;
    const int p   = seq & (P - 1);
    const float2 a = g_Lbar[p];
    const int t = threadIdx.x;
    const int lane = t & 31, w = t >> 5;

    const float4* rre = (const float4*)(g_S + ((size_t)b * K2 + p) * LSEQ + t * 16);
    const float4* rim = (const float4*)(g_S + ((size_t)b * K2 + P + p) * LSEQ + t * 16);

    float2 x[16];
#pragma unroll
    for (int i = 0; i < 4; i++) {
        float4 vr = rre[i], vi = rim[i];
        x[4 * i + 0] = make_float2(vr.x, vi.x);
        x[4 * i + 1] = make_float2(vr.y, vi.y);
        x[4 * i + 2] = make_float2(vr.z, vi.z);
        x[4 * i + 3] = make_float2(vr.w, vi.w);
    }

    float2 v = make_float2(0.f, 0.f);
#pragma unroll
    for (int j = 0; j < 16; j++) {
        float2 av = cmul(a, v);
        v = make_float2(av.x + x[j].x, av.y + x[j].y);
        x[j] = v;
    }

    float2 a16 = cmul(a, a); a16 = cmul(a16, a16); a16 = cmul(a16, a16); a16 = cmul(a16, a16);

    float2 f = a16;
    float2 vi2 = v;
#pragma unroll
    for (int d = 1; d < 32; d <<= 1) {
        float px = __shfl_up_sync(0xffffffffu, vi2.x, d);
        float py = __shfl_up_sync(0xffffffffu, vi2.y, d);
        if (lane >= d) {
            float2 add = cmul(f, make_float2(px, py));
            vi2.x += add.x; vi2.y += add.y;
        }
        f = cmul(f, f);
    }
    float ex = __shfl_up_sync(0xffffffffu, vi2.x, 1);
    float ey = __shfl_up_sync(0xffffffffu, vi2.y, 1);
    float2 vex = (lane == 0) ? make_float2(0.f, 0.f) : make_float2(ex, ey);

    __shared__ float2 wsum[16];
    __shared__ float2 wpre[16];
    if (lane == 31) wsum[w] = vi2;
    __syncthreads();

    float2 a512 = cmul(a16, a16); a512 = cmul(a512, a512); a512 = cmul(a512, a512);
    a512 = cmul(a512, a512); a512 = cmul(a512, a512);

    if (w == 0) {
        float2 s = (lane < 16) ? wsum[lane] : make_float2(0.f, 0.f);
        float2 g = a512;
#pragma unroll
        for (int d = 1; d < 16; d <<= 1) {
            float px = __shfl_up_sync(0xffffffffu, s.x, d);
            float py = __shfl_up_sync(0xffffffffu, s.y, d);
            if (lane >= d) {
                float2 add = cmul(g, make_float2(px, py));
                s.x += add.x; s.y += add.y;
            }
            g = cmul(g, g);
        }
        float qx = __shfl_up_sync(0xffffffffu, s.x, 1);
        float qy = __shfl_up_sync(0xffffffffu, s.y, 1);
        if (lane < 16) wpre[lane] = (lane == 0) ? make_float2(0.f, 0.f) : make_float2(qx, qy);
    }
    __syncthreads();

    float2 pw16 = make_float2(1.f, 0.f);
    {
        float2 base = a16; int e = lane;
#pragma unroll
        for (int it = 0; it < 5; it++) {
            if (e & 1) pw16 = cmul(pw16, base);
            base = cmul(base, base);
            e >>= 1;
        }
    }
    float2 wc = wpre[w];
    float2 s0 = cmul(pw16, wc);
    s0.x += vex.x; s0.y += vex.y;

    float2 pw = a;
#pragma unroll
    for (int j = 0; j < 16; j++) {
        float2 add = cmul(pw, s0);
        x[j].x += add.x; x[j].y += add.y;
        pw = cmul(pw, a);
    }

    // write fp16 planes (coalesced 32B per thread per row)
    __half2 hre[8], him[8];
#pragma unroll
    for (int j = 0; j < 8; j++) {
        hre[j] = __floats2half2_rn(x[2 * j].x, x[2 * j + 1].x);
        him[j] = __floats2half2_rn(x[2 * j].y, x[2 * j + 1].y);
    }
    __half* dre = g_Xh + ((size_t)b * K2 + p) * LSEQ + t * 16;
    __half* dim = g_Xh + ((size_t)b * K2 + P + p) * LSEQ + t * 16;
    ((uint4*)dre)[0] = ((uint4*)hre)[0];
    ((uint4*)dre)[1] = ((uint4*)hre)[1];
    ((uint4*)dim)[0] = ((uint4*)him)[0];
    ((uint4*)dim)[1] = ((uint4*)him)[1];
}

// ---------------------------------------------------------------------------
extern "C" void kernel_launch(void* const* d_in, const int* in_sizes, int n_in,
                              void* d_out, int out_size) {
    const float* u   = (const float*)d_in[0];
    const float* Lre = (const float*)d_in[1];
    const float* Lim = (const float*)d_in[2];
    const float* Bm  = (const float*)d_in[3];
    const float* Cm  = (const float*)d_in[4];
    const float* D   = (const float*)d_in[5];
    const float* ls  = (const float*)d_in[6];
    float* out = (float*)d_out;

    cudaFuncSetAttribute(bu_mma_kernel,  cudaFuncAttributeMaxDynamicSharedMemorySize, SMEM_K1);
    cudaFuncSetAttribute(out_mma_kernel, cudaFuncAttributeMaxDynamicSharedMemorySize, SMEM_K3);

    setup_kernel<<<256, 256>>>(Lre, Lim, Bm, Cm, ls);

    uconv_kernel<<<(unsigned)((size_t)BSZ * H * LSEQ / (256 * 8)), 256>>>(u);

    bu_mma_kernel<<<dim3(LSEQ / 128, 1, BSZ), 256, SMEM_K1>>>();

    scan_kernel<<<BSZ * P, 512>>>();

    out_mma_kernel<<<dim3(LSEQ / 128, 4, BSZ), 256, SMEM_K3>>>(u, D, out);
}

// round 11
// speedup vs baseline: 4.1231x; 1.2865x over previous
#include <cuda_runtime.h>
#include <cuda_fp16.h>
#include <stdint.h>
#include <math.h>

#define BSZ  8
#define H    512
#define P    128
#define LSEQ 8192
#define K2   256          // 2P

// ---------------- scratch (__device__ globals; allocation-free rule) --------
__device__ __align__(16) __half g_uH[(size_t)BSZ * H * LSEQ];   // u fp16 [b][h][l]
__device__ __align__(16) float  g_S [(size_t)BSZ * K2 * LSEQ];  // Bu fp32 [b][2p][l]
__device__ __align__(16) __half g_Xh[(size_t)BSZ * K2 * LSEQ];  // xs fp16 [b][2p][l]
__device__ __align__(16) __half g_W [K2 * H];                   // Bst fp16 [2p][h]
__device__ __align__(16) __half g_C [H * K2];                   // folded C fp16 [h][2p]
__device__ float2 g_Lbar[P];

// ---------------- helpers ---------------------------------------------------
__device__ __forceinline__ float2 cmul(float2 a, float2 b) {
    return make_float2(a.x * b.x - a.y * b.y, a.x * b.y + a.y * b.x);
}
__device__ __forceinline__ unsigned smem_u32(const void* p) {
    return (unsigned)__cvta_generic_to_shared(p);
}
__device__ __forceinline__ void cp16(unsigned s, const void* g) {
    asm volatile("cp.async.cg.shared.global [%0], [%1], 16;\n" :: "r"(s), "l"(g));
}
__device__ __forceinline__ void cp_commit() { asm volatile("cp.async.commit_group;\n"); }
__device__ __forceinline__ void cp_wait0()  { asm volatile("cp.async.wait_group 0;\n"); }
__device__ __forceinline__ void cp_wait1()  { asm volatile("cp.async.wait_group 1;\n"); }

#define LDSM_X4(r0, r1, r2, r3, a)                                              \
    asm volatile("ldmatrix.sync.aligned.m8n8.x4.shared.b16 {%0,%1,%2,%3}, [%4];"\
                 : "=r"(r0), "=r"(r1), "=r"(r2), "=r"(r3) : "r"(a))
#define LDSM_X4_T(r0, r1, r2, r3, a)                                            \
    asm volatile("ldmatrix.sync.aligned.m8n8.x4.trans.shared.b16 {%0,%1,%2,%3}, [%4];"\
                 : "=r"(r0), "=r"(r1), "=r"(r2), "=r"(r3) : "r"(a))

#define MMA16816(c, a, b)                                                       \
    asm volatile("mma.sync.aligned.m16n8k16.row.col.f32.f16.f16.f32 "           \
                 "{%0,%1,%2,%3}, {%4,%5,%6,%7}, {%8,%9}, {%0,%1,%2,%3};"        \
                 : "+f"((c)[0]), "+f"((c)[1]), "+f"((c)[2]), "+f"((c)[3])       \
                 : "r"((a)[0]), "r"((a)[1]), "r"((a)[2]), "r"((a)[3]),          \
                   "r"((b)[0]), "r"((b)[1]))

// A rows: 32 halfs = 64B + 16B pad = 80B stride (conflict-free ldmatrix)
// B tile: 32 k-rows x 136 halfs = 272B stride (conflict-free trans ldmatrix)

// ---------------------------------------------------------------------------
// Setup: Lambda_bar, fp16 stacked Bbar [2p][h], fp16 folded C [h][2p].
// ---------------------------------------------------------------------------
__global__ void setup_kernel(const float* __restrict__ Lre, const float* __restrict__ Lim,
                             const float* __restrict__ Bm, const float* __restrict__ Cm,
                             const float* __restrict__ logstep) {
    int tid = blockIdx.x * blockDim.x + threadIdx.x;
    int stride = gridDim.x * blockDim.x;

    if (tid < P) {
        double st = exp((double)logstep[tid]);
        double zre = (double)Lre[tid] * st, zim = (double)Lim[tid] * st;
        double er = exp(zre);
        g_Lbar[tid] = make_float2((float)(er * cos(zim)), (float)(er * sin(zim)));
    }

    for (int i = tid; i < P * H; i += stride) {
        int p = i >> 9, h = i & (H - 1);
        double st  = exp((double)logstep[p]);
        double lre = (double)Lre[p], lim = (double)Lim[p];
        double zre = lre * st, zim = lim * st;
        double er  = exp(zre);
        double numr = er * cos(zim) - 1.0;
        double numi = er * sin(zim);
        double den  = lre * lre + lim * lim;
        double gre = (numr * lre + numi * lim) / den;
        double gim = (numi * lre - numr * lim) / den;
        float br = Bm[2 * i], bi = Bm[2 * i + 1];
        float vre = (float)(gre * (double)br - gim * (double)bi);
        float vim = (float)(gre * (double)bi + gim * (double)br);
        g_W[p * H + h]       = __float2half_rn(vre);
        g_W[(P + p) * H + h] = __float2half_rn(vim);
    }

    for (int i = tid; i < H * K2; i += stride) {
        int h = i >> 8, k = i & (K2 - 1);
        float v = (k < P) ? 2.0f * Cm[(h * P + k) * 2]
                          : -2.0f * Cm[(h * P + (k - P)) * 2 + 1];
        g_C[(size_t)h * K2 + k] = __float2half_rn(v);
    }
}

// ---------------------------------------------------------------------------
// u fp32 -> fp16, same layout (elementwise, fully coalesced).
// ---------------------------------------------------------------------------
__global__ void __launch_bounds__(256) uconv_kernel(const float* __restrict__ u) {
    size_t i = ((size_t)blockIdx.x * 256 + threadIdx.x) * 8;
    float4 a = *(const float4*)(u + i);
    float4 b = *(const float4*)(u + i + 4);
    __half2 h[4];
    h[0] = __floats2half2_rn(a.x, a.y);
    h[1] = __floats2half2_rn(a.z, a.w);
    h[2] = __floats2half2_rn(b.x, b.y);
    h[3] = __floats2half2_rn(b.z, b.w);
    *(uint4*)(g_uH + i) = *(uint4*)h;
}

// ---------------------------------------------------------------------------
// Shared MMA mainloop: C[MROWS x 128] = W[MROWS x KD] * Bg[KD x 128] (fp16),
// W K-major, Bg natural [k][L] via ldmatrix.trans.
// 8 warps as 4(m) x 2(n); warp tile (MT*16) x 64. Double-buffered cp.async.
// ---------------------------------------------------------------------------
template <int KD, int MROWS, int MT>
__device__ __forceinline__ void mma_mainloop(
    const __half* __restrict__ W,
    const __half* __restrict__ Bg, int l0,
    unsigned sbase, int tid, int wid, int lane, float c[MT][8][4])
{
    constexpr int AB   = MROWS * 80;
    constexpr int BOFF = AB;
    constexpr int STG  = BOFF + 32 * 272;
    const int wr = wid >> 1, wc = wid & 1;
    const int m0w = wr * (MT * 16);
    const int n0w = wc * 64;
    constexpr int NCH = KD / 32;

    auto load_stage = [&](int buf, int k0) {
        unsigned sb = sbase + buf * STG;
        for (int s = tid; s < MROWS * 4; s += 256) {
            int r = s >> 2, seg = s & 3;
            cp16(sb + r * 80 + seg * 16, W + (size_t)r * KD + k0 + seg * 8);
        }
        for (int s = tid; s < 512; s += 256) {
            int r = s >> 4, seg = s & 15;
            cp16(sb + BOFF + r * 272 + seg * 16,
                 Bg + (size_t)(k0 + r) * LSEQ + l0 + seg * 8);
        }
        cp_commit();
    };

    load_stage(0, 0);
    load_stage(1, 32);

    for (int ch = 0; ch < NCH; ch++) {
        if (ch < NCH - 1) cp_wait1(); else cp_wait0();
        __syncthreads();
        unsigned sb = sbase + (ch & 1) * STG;

#pragma unroll
        for (int ks = 0; ks < 2; ks++) {
            unsigned aH[MT][4];
            unsigned koff = ks * 32 + (lane >> 4) * 16;
#pragma unroll
            for (int mt = 0; mt < MT; mt++) {
                unsigned ra = sb + (m0w + mt * 16 + (lane & 15)) * 80 + koff;
                LDSM_X4(aH[mt][0], aH[mt][1], aH[mt][2], aH[mt][3], ra);
            }
            unsigned b[8][2];
#pragma unroll
            for (int np = 0; np < 4; np++) {
                unsigned rb = sb + BOFF + (ks * 16 + (lane & 15)) * 272
                            + (n0w + np * 16 + (lane >> 4) * 8) * 2;
                unsigned t0, t1, t2, t3;
                LDSM_X4_T(t0, t1, t2, t3, rb);
                b[2 * np][0]     = t0; b[2 * np][1]     = t1;
                b[2 * np + 1][0] = t2; b[2 * np + 1][1] = t3;
            }
#pragma unroll
            for (int mt = 0; mt < MT; mt++)
#pragma unroll
                for (int nt = 0; nt < 8; nt++)
                    MMA16816(c[mt][nt], aH[mt], b[nt]);
        }
        __syncthreads();
        if (ch + 2 < NCH) load_stage(ch & 1, (ch + 2) * 32);
    }
}

#define SMEM_K1 (2 * (256 * 80 + 32 * 272))   // 58368
#define SMEM_K3 (2 * (128 * 80 + 32 * 272))   // 37888

// ---------------------------------------------------------------------------
// K1: Bu planes. C[2p(256) x l(128)] = Bst * u. Direct plane writes.
// ---------------------------------------------------------------------------
__global__ void __launch_bounds__(256, 1) bu_mma_kernel() {
    extern __shared__ __align__(16) char dsm[];
    const unsigned sbase = smem_u32(dsm);
    const int b = blockIdx.z, l0 = blockIdx.x * 128;
    const int tid = threadIdx.x, wid = tid >> 5, lane = tid & 31;

    float c[4][8][4] = {};
    mma_mainloop<H, 256, 4>(g_W, g_uH + (size_t)b * H * LSEQ,
                            l0, sbase, tid, wid, lane, c);

    const int wr = wid >> 1, wc = wid & 1;
    const int m0w = wr * 64, n0w = wc * 64;
#pragma unroll
    for (int mt = 0; mt < 4; mt++)
#pragma unroll
        for (int nt = 0; nt < 8; nt++) {
            int row = m0w + mt * 16 + (lane >> 2);
            int col = n0w + nt * 8 + (lane & 3) * 2;
            float* dst = g_S + ((size_t)b * K2 + row) * LSEQ + l0 + col;
            *(float2*)dst = make_float2(c[mt][nt][0], c[mt][nt][1]);
            *(float2*)(dst + (size_t)8 * LSEQ) = make_float2(c[mt][nt][2], c[mt][nt][3]);
        }
}

// ---------------------------------------------------------------------------
// K3: out. C[h(128) x l(128)] = C2 * xs; epilogue + D*u + exact gelu.
// ---------------------------------------------------------------------------
__global__ void __launch_bounds__(256, 1) out_mma_kernel(const float* __restrict__ u,
                                                         const float* __restrict__ Dv,
                                                         float* __restrict__ out) {
    extern __shared__ __align__(16) char dsm[];
    const unsigned sbase = smem_u32(dsm);
    const int b = blockIdx.z, l0 = blockIdx.x * 128, h0 = blockIdx.y * 128;
    const int tid = threadIdx.x, wid = tid >> 5, lane = tid & 31;

    float c[2][8][4] = {};
    mma_mainloop<K2, 128, 2>(g_C + (size_t)h0 * K2,
                             g_Xh + (size_t)b * K2 * LSEQ,
                             l0, sbase, tid, wid, lane, c);

    const int wr = wid >> 1, wc = wid & 1;
    const int m0w = wr * 32, n0w = wc * 64;
#pragma unroll
    for (int mt = 0; mt < 2; mt++)
#pragma unroll
        for (int nt = 0; nt < 8; nt++) {
            int row = m0w + mt * 16 + (lane >> 2);
            int col = n0w + nt * 8 + (lane & 3) * 2;
            int h = h0 + row;
            size_t o = ((size_t)b * H + h) * LSEQ + l0 + col;

            float2 uv = *(const float2*)(u + o);
            float dd = Dv[h];
            float v0 = c[mt][nt][0] + dd * uv.x;
            float v1 = c[mt][nt][1] + dd * uv.y;
            v0 = 0.5f * v0 * (1.0f + erff(v0 * 0.70710678118654752f));
            v1 = 0.5f * v1 * (1.0f + erff(v1 * 0.70710678118654752f));
            *(float2*)(out + o) = make_float2(v0, v1);

            size_t o2 = o + (size_t)8 * LSEQ;
            float2 uw = *(const float2*)(u + o2);
            float de = Dv[h + 8];
            float v2 = c[mt][nt][2] + de * uw.x;
            float v3 = c[mt][nt][3] + de * uw.y;
            v2 = 0.5f * v2 * (1.0f + erff(v2 * 0.70710678118654752f));
            v3 = 0.5f * v3 * (1.0f + erff(v3 * 0.70710678118654752f));
            *(float2*)(out + o2) = make_float2(v2, v3);
        }
}

// ---------------------------------------------------------------------------
// Scan along L per (b,p); warp-shuffle Kogge-Stone; fp32 in, fp16 planes out.
// ---------------------------------------------------------------------------
__global__ void __launch_bounds__(512) scan_kernel() {
    const int seq = blockIdx.x;          // b*P + p
    const int b   = seq >> 7;
    const int p   = seq & (P - 1);
    const float2 a = g_Lbar[p];
    const int t = threadIdx.x;
    const int lane = t & 31, w = t >> 5;

    const float4* rre = (const float4*)(g_S + ((size_t)b * K2 + p) * LSEQ + t * 16);
    const float4* rim = (const float4*)(g_S + ((size_t)b * K2 + P + p) * LSEQ + t * 16);

    float2 x[16];
#pragma unroll
    for (int i = 0; i < 4; i++) {
        float4 vr = rre[i], vi = rim[i];
        x[4 * i + 0] = make_float2(vr.x, vi.x);
        x[4 * i + 1] = make_float2(vr.y, vi.y);
        x[4 * i + 2] = make_float2(vr.z, vi.z);
        x[4 * i + 3] = make_float2(vr.w, vi.w);
    }

    float2 v = make_float2(0.f, 0.f);
#pragma unroll
    for (int j = 0; j < 16; j++) {
        float2 av = cmul(a, v);
        v = make_float2(av.x + x[j].x, av.y + x[j].y);
        x[j] = v;
    }

    float2 a16 = cmul(a, a); a16 = cmul(a16, a16); a16 = cmul(a16, a16); a16 = cmul(a16, a16);

    float2 f = a16;
    float2 vi2 = v;
#pragma unroll
    for (int d = 1; d < 32; d <<= 1) {
        float px = __shfl_up_sync(0xffffffffu, vi2.x, d);
        float py = __shfl_up_sync(0xffffffffu, vi2.y, d);
        if (lane >= d) {
            float2 add = cmul(f, make_float2(px, py));
            vi2.x += add.x; vi2.y += add.y;
        }
        f = cmul(f, f);
    }
    float ex = __shfl_up_sync(0xffffffffu, vi2.x, 1);
    float ey = __shfl_up_sync(0xffffffffu, vi2.y, 1);
    float2 vex = (lane == 0) ? make_float2(0.f, 0.f) : make_float2(ex, ey);

    __shared__ float2 wsum[16];
    __shared__ float2 wpre[16];
    if (lane == 31) wsum[w] = vi2;
    __syncthreads();

    float2 a512 = cmul(a16, a16); a512 = cmul(a512, a512); a512 = cmul(a512, a512);
    a512 = cmul(a512, a512); a512 = cmul(a512, a512);

    if (w == 0) {
        float2 s = (lane < 16) ? wsum[lane] : make_float2(0.f, 0.f);
        float2 g = a512;
#pragma unroll
        for (int d = 1; d < 16; d <<= 1) {
            float px = __shfl_up_sync(0xffffffffu, s.x, d);
            float py = __shfl_up_sync(0xffffffffu, s.y, d);
            if (lane >= d) {
                float2 add = cmul(g, make_float2(px, py));
                s.x += add.x; s.y += add.y;
            }
            g = cmul(g, g);
        }
        float qx = __shfl_up_sync(0xffffffffu, s.x, 1);
        float qy = __shfl_up_sync(0xffffffffu, s.y, 1);
        if (lane < 16) wpre[lane] = (lane == 0) ? make_float2(0.f, 0.f) : make_float2(qx, qy);
    }
    __syncthreads();

    float2 pw16 = make_float2(1.f, 0.f);
    {
        float2 base = a16; int e = lane;
#pragma unroll
        for (int it = 0; it < 5; it++) {
            if (e & 1) pw16 = cmul(pw16, base);
            base = cmul(base, base);
            e >>= 1;
        }
    }
    float2 wc = wpre[w];
    float2 s0 = cmul(pw16, wc);
    s0.x += vex.x; s0.y += vex.y;

    float2 pw = a;
#pragma unroll
    for (int j = 0; j < 16; j++) {
        float2 add = cmul(pw, s0);
        x[j].x += add.x; x[j].y += add.y;
        pw = cmul(pw, a);
    }

    // write fp16 planes (coalesced 32B per thread per row)
    __half2 hre[8], him[8];
#pragma unroll
    for (int j = 0; j < 8; j++) {
        hre[j] = __floats2half2_rn(x[2 * j].x, x[2 * j + 1].x);
        him[j] = __floats2half2_rn(x[2 * j].y, x[2 * j + 1].y);
    }
    __half* dre = g_Xh + ((size_t)b * K2 + p) * LSEQ + t * 16;
    __half* dim = g_Xh + ((size_t)b * K2 + P + p) * LSEQ + t * 16;
    ((uint4*)dre)[0] = ((uint4*)hre)[0];
    ((uint4*)dre)[1] = ((uint4*)hre)[1];
    ((uint4*)dim)[0] = ((uint4*)him)[0];
    ((uint4*)dim)[1] = ((uint4*)him)[1];
}

// ---------------------------------------------------------------------------
extern "C" void kernel_launch(void* const* d_in, const int* in_sizes, int n_in,
                              void* d_out, int out_size) {
    const float* u   = (const float*)d_in[0];
    const float* Lre = (const float*)d_in[1];
    const float* Lim = (const float*)d_in[2];
    const float* Bm  = (const float*)d_in[3];
    const float* Cm  = (const float*)d_in[4];
    const float* D   = (const float*)d_in[5];
    const float* ls  = (const float*)d_in[6];
    float* out = (float*)d_out;

    cudaFuncSetAttribute(bu_mma_kernel,  cudaFuncAttributeMaxDynamicSharedMemorySize, SMEM_K1);
    cudaFuncSetAttribute(out_mma_kernel, cudaFuncAttributeMaxDynamicSharedMemorySize, SMEM_K3);

    setup_kernel<<<256, 256>>>(Lre, Lim, Bm, Cm, ls);

    uconv_kernel<<<(unsigned)((size_t)BSZ * H * LSEQ / (256 * 8)), 256>>>(u);

    bu_mma_kernel<<<dim3(LSEQ / 128, 1, BSZ), 256, SMEM_K1>>>();

    scan_kernel<<<BSZ * P, 512>>>();

    out_mma_kernel<<<dim3(LSEQ / 128, 4, BSZ), 256, SMEM_K3>>>(u, D, out);
}